// round 1
// baseline (speedup 1.0000x reference)
#include <cuda_runtime.h>
#include <cstdint>
#include <cstddef>

#define BZ   256
#define SEQ  512
#define INS  256
#define HID  256

// ---------------------------------------------------------------------------
// helpers: packed f32x2 FMA (Blackwell), pack/unpack, DSMEM store, cluster sync
// ---------------------------------------------------------------------------
__device__ __forceinline__ void ffma2(unsigned long long &acc,
                                      unsigned long long a,
                                      unsigned long long b) {
    asm volatile("fma.rn.f32x2 %0, %1, %2, %0;" : "+l"(acc) : "l"(a), "l"(b));
}
__device__ __forceinline__ unsigned long long pack2(float x, float y) {
    unsigned long long r;
    asm("mov.b64 %0, {%1, %2};" : "=l"(r) : "f"(x), "f"(y));
    return r;
}
__device__ __forceinline__ float2 unpack2(unsigned long long v) {
    float2 f;
    asm("mov.b64 {%0, %1}, %2;" : "=f"(f.x), "=f"(f.y) : "l"(v));
    return f;
}
__device__ __forceinline__ unsigned smem_u32(const void* p) {
    unsigned a;
    asm("{ .reg .u64 t; cvta.to.shared.u64 t, %1; cvt.u32.u64 %0, t; }"
        : "=r"(a) : "l"(p));
    return a;
}
__device__ __forceinline__ unsigned mapa_peer(unsigned addr, unsigned peer) {
    unsigned r;
    asm("mapa.shared::cluster.u32 %0, %1, %2;" : "=r"(r) : "r"(addr), "r"(peer));
    return r;
}
__device__ __forceinline__ void st_cluster_f32(unsigned addr, float v) {
    asm volatile("st.shared::cluster.f32 [%0], %1;" :: "r"(addr), "f"(v));
}
__device__ __forceinline__ void cluster_sync_() {
    asm volatile("barrier.cluster.arrive.aligned;" ::: "memory");
    asm volatile("barrier.cluster.wait.aligned;" ::: "memory");
}

// ---------------------------------------------------------------------------
// Kernel 1: XU = X @ U + bias  ->  written into decoder region of d_out
// C[M=131072, N=256], K=256. 128x128 CTA tile, 256 thr, 8(M)x8(N) per thread,
// f32x2-packed along N. Double-buffered k-tiles of 16.
// ---------------------------------------------------------------------------
__global__ void __launch_bounds__(256, 2) xu_kernel(
    const float* __restrict__ X, const float* __restrict__ U,
    const float* __restrict__ bias, float* __restrict__ C)
{
    __shared__ float Xs[2][16][128];   // [k][m]  (m contiguous)
    __shared__ float Us[2][16][128];   // [k][n]  (n contiguous)

    const int tid    = threadIdx.x;
    const int m_base = blockIdx.x * 128;
    const int n_base = blockIdx.y * 128;
    const int tx = tid & 15;          // n group
    const int ty = tid >> 4;          // m group
    const int m0 = ty * 8;
    const int n0 = tx * 8;

    // load mappings
    const int lmx = tid >> 1;            // 0..127 (X row within tile)
    const int lkx = (tid & 1) * 8;       // 0 or 8 (k offset)
    const int lku = tid >> 4;            // 0..15  (U row = k)
    const int lnu = (tid & 15) * 8;      // n offset

    const float* Xg = X + (size_t)(m_base + lmx) * 256 + lkx;
    const float* Ug = U + (size_t)lku * 256 + n_base + lnu;

    float4 xa = *(const float4*)(Xg + 0);
    float4 xb = *(const float4*)(Xg + 4);
    float4 ua = *(const float4*)(Ug + 0);
    float4 ub = *(const float4*)(Ug + 4);

    int buf = 0;
    // stage tile 0
    Xs[0][lkx + 0][lmx] = xa.x;  Xs[0][lkx + 1][lmx] = xa.y;
    Xs[0][lkx + 2][lmx] = xa.z;  Xs[0][lkx + 3][lmx] = xa.w;
    Xs[0][lkx + 4][lmx] = xb.x;  Xs[0][lkx + 5][lmx] = xb.y;
    Xs[0][lkx + 6][lmx] = xb.z;  Xs[0][lkx + 7][lmx] = xb.w;
    *(float4*)&Us[0][lku][lnu]     = ua;
    *(float4*)&Us[0][lku][lnu + 4] = ub;
    __syncthreads();

    unsigned long long acc[8][4];
#pragma unroll
    for (int i = 0; i < 8; i++)
#pragma unroll
        for (int j = 0; j < 4; j++) acc[i][j] = 0ULL;

    for (int kt = 0; kt < 16; kt++) {
        if (kt < 15) {
            const float* Xg2 = Xg + (kt + 1) * 16;
            const float* Ug2 = Ug + (size_t)(kt + 1) * 16 * 256;
            xa = *(const float4*)(Xg2 + 0);
            xb = *(const float4*)(Xg2 + 4);
            ua = *(const float4*)(Ug2 + 0);
            ub = *(const float4*)(Ug2 + 4);
        }
#pragma unroll
        for (int k = 0; k < 16; k++) {
            float a[8];
            *(float4*)&a[0] = *(const float4*)&Xs[buf][k][m0];
            *(float4*)&a[4] = *(const float4*)&Xs[buf][k][m0 + 4];
            ulonglong2 bq0 = *(const ulonglong2*)&Us[buf][k][n0];
            ulonglong2 bq1 = *(const ulonglong2*)&Us[buf][k][n0 + 4];
            unsigned long long bb[4] = {bq0.x, bq0.y, bq1.x, bq1.y};
#pragma unroll
            for (int i = 0; i < 8; i++) {
                unsigned long long a2 = pack2(a[i], a[i]);
                ffma2(acc[i][0], a2, bb[0]);
                ffma2(acc[i][1], a2, bb[1]);
                ffma2(acc[i][2], a2, bb[2]);
                ffma2(acc[i][3], a2, bb[3]);
            }
        }
        if (kt < 15) {
            int nb = buf ^ 1;
            Xs[nb][lkx + 0][lmx] = xa.x;  Xs[nb][lkx + 1][lmx] = xa.y;
            Xs[nb][lkx + 2][lmx] = xa.z;  Xs[nb][lkx + 3][lmx] = xa.w;
            Xs[nb][lkx + 4][lmx] = xb.x;  Xs[nb][lkx + 5][lmx] = xb.y;
            Xs[nb][lkx + 6][lmx] = xb.z;  Xs[nb][lkx + 7][lmx] = xb.w;
            *(float4*)&Us[nb][lku][lnu]     = ua;
            *(float4*)&Us[nb][lku][lnu + 4] = ub;
            __syncthreads();
            buf = nb;
        }
    }

    // epilogue: add bias, store
    float b8[8];
    *(float4*)&b8[0] = *(const float4*)(bias + n_base + n0);
    *(float4*)&b8[4] = *(const float4*)(bias + n_base + n0 + 4);
#pragma unroll
    for (int i = 0; i < 8; i++) {
        float* Cr = C + (size_t)(m_base + m0 + i) * 256 + n_base + n0;
#pragma unroll
        for (int j = 0; j < 4; j++) {
            float2 p = unpack2(acc[i][j]);
            p.x += b8[2 * j];
            p.y += b8[2 * j + 1];
            *(float2*)(Cr + 2 * j) = p;
        }
    }
}

// ---------------------------------------------------------------------------
// Kernel 2: sequential recurrence. 64 clusters x 2 CTAs, 256 thr/CTA.
// Cluster c owns batch rows 4c..4c+3. CTA rank r owns output cols r*128..+127
// and holds V^T for those cols in SMEM (fp32, KPAD=260 for bank-conflict-free
// strided LDS.128). Per step: K-split f32x2 dot products, SMEM reduction,
// tanh, DSMEM exchange of h halves, one cluster barrier.
// ---------------------------------------------------------------------------
#define KPAD 260
#define RNN_SMEM_FLOATS (128 * KPAD + 2 * 4 * 256 + 8 * 512)
#define RNN_SMEM_BYTES  (RNN_SMEM_FLOATS * 4)

__global__ void __launch_bounds__(256, 1) __cluster_dims__(2, 1, 1)
rnn_kernel(const float* __restrict__ enc, const float* __restrict__ V,
           float* __restrict__ dec)
{
    extern __shared__ float smem[];
    float* Vs  = smem;                    // [128][KPAD]
    float* hb  = Vs + 128 * KPAD;         // [2][4][256]
    float* red = hb + 2 * 4 * 256;        // [8][512]

    const int tid = threadIdx.x;
    const int w   = tid >> 5;             // warp -> k section (32 k each)
    const int l   = tid & 31;
    unsigned rk;
    asm("mov.u32 %0, %%cluster_ctarank;" : "=r"(rk));
    const unsigned peer = rk ^ 1u;
    const int cid = (int)(blockIdx.x >> 1);
    const int b0  = cid * 4;
    const int c0  = (int)rk * 128;

    // --- load V^T half: Vs[c][k] = V[k][c0+c]
    for (int i = tid; i < 128 * 256; i += 256) {
        int cl = i & 127, k = i >> 7;
        Vs[cl * KPAD + k] = V[(size_t)k * HID + c0 + cl];
    }
    // --- h0 = encoder rows (both CTAs load full h)
    for (int i = tid; i < 4 * 256; i += 256) {
        hb[i] = enc[(size_t)b0 * HID + i];
    }
    __syncthreads();
    cluster_sync_();

    // epilogue mapping: thread -> col ec, rows er0 and er0+2
    const int ec  = tid & 127;
    const int er0 = tid >> 7;     // 0 or 1
    const size_t o1b = ((size_t)(b0 + er0)     * SEQ) * HID + c0 + ec;
    const size_t o2b = ((size_t)(b0 + er0 + 2) * SEQ) * HID + c0 + ec;
    const int hi1 = er0 * 256 + c0 + ec;   // within one h buffer [4][256]
    const int hi2 = hi1 + 512;

    // precompute peer DSMEM addresses for both buffers
    const unsigned hb_a = smem_u32(hb);
    const unsigned pa[4] = {
        mapa_peer(hb_a + (unsigned)(hi1) * 4u, peer),
        mapa_peer(hb_a + (unsigned)(hi2) * 4u, peer),
        mapa_peer(hb_a + (unsigned)(1024 + hi1) * 4u, peer),
        mapa_peer(hb_a + (unsigned)(1024 + hi2) * 4u, peer)
    };

    const int k0 = w * 32;
    int cur = 0;

    for (int t = 0; t < SEQ; t++) {
        // prefetch xu (pre-written into dec by xu_kernel; overwritten below)
        const float xu1 = dec[o1b + (size_t)t * HID];
        const float xu2 = dec[o2b + (size_t)t * HID];

        // ---- partial dot products: rows 0..3, cols {l, l+32, l+64, l+96},
        //      k in [k0, k0+32), packed pairs over k
        const float* hc = hb + cur * 1024;
        unsigned long long acc[16];
#pragma unroll
        for (int i = 0; i < 16; i++) acc[i] = 0ULL;

#pragma unroll
        for (int kk = 0; kk < 32; kk += 4) {
            const int k = k0 + kk;
            ulonglong2 hr[4], vc[4];
#pragma unroll
            for (int r = 0; r < 4; r++)
                hr[r] = *(const ulonglong2*)(hc + r * 256 + k);
#pragma unroll
            for (int c = 0; c < 4; c++)
                vc[c] = *(const ulonglong2*)(Vs + (l + 32 * c) * KPAD + k);
#pragma unroll
            for (int r = 0; r < 4; r++)
#pragma unroll
                for (int c = 0; c < 4; c++) {
                    ffma2(acc[r * 4 + c], hr[r].x, vc[c].x);
                    ffma2(acc[r * 4 + c], hr[r].y, vc[c].y);
                }
        }

        // ---- stage partials: red[w][r*128 + c*32 + l]
#pragma unroll
        for (int r = 0; r < 4; r++)
#pragma unroll
            for (int c = 0; c < 4; c++) {
                float2 p = unpack2(acc[r * 4 + c]);
                red[w * 512 + r * 128 + c * 32 + l] = p.x + p.y;
            }
        __syncthreads();

        // ---- reduce over 8 k-sections, tanh, write out + exchange
        const int o1 = er0 * 128 + ec;
        const int o2 = o1 + 256;
        float s1 = 0.f, s2 = 0.f;
#pragma unroll
        for (int ww = 0; ww < 8; ww++) {
            s1 += red[ww * 512 + o1];
            s2 += red[ww * 512 + o2];
        }
        const float v1 = tanhf(s1 + xu1);
        const float v2 = tanhf(s2 + xu2);

        dec[o1b + (size_t)t * HID] = v1;
        dec[o2b + (size_t)t * HID] = v2;

        const int nxt = cur ^ 1;
        float* hn = hb + nxt * 1024;
        hn[hi1] = v1;
        hn[hi2] = v2;
        st_cluster_f32(pa[nxt * 2 + 0], v1);
        st_cluster_f32(pa[nxt * 2 + 1], v2);

        cluster_sync_();   // release own writes / acquire peer's half
        cur = nxt;
    }
}

// ---------------------------------------------------------------------------
// launch
// ---------------------------------------------------------------------------
extern "C" void kernel_launch(void* const* d_in, const int* in_sizes, int n_in,
                              void* d_out, int out_size)
{
    const float* enc  = (const float*)d_in[0];   // [256,256]
    const float* xdec = (const float*)d_in[1];   // [256,512,256]
    const float* U    = (const float*)d_in[2];   // [256,256]
    const float* V    = (const float*)d_in[3];   // [256,256]
    const float* b    = (const float*)d_in[4];   // [256]

    float* out = (float*)d_out;
    float* dec = out + (size_t)BZ * HID;         // decoder_outputs region

    // output[0] = encoder_inputs passthrough
    cudaMemcpyAsync(out, enc, (size_t)BZ * HID * sizeof(float),
                    cudaMemcpyDeviceToDevice, 0);

    // XU + bias -> dec (in-place scratch, overwritten by recurrence)
    xu_kernel<<<dim3((BZ * SEQ) / 128, HID / 128), 256>>>(xdec, U, b, dec);

    // sequential recurrence
    cudaFuncSetAttribute(rnn_kernel,
                         cudaFuncAttributeMaxDynamicSharedMemorySize,
                         RNN_SMEM_BYTES);
    rnn_kernel<<<128, 256, RNN_SMEM_BYTES>>>(enc, V, dec);
}

// round 3
// speedup vs baseline: 1.0600x; 1.0600x over previous
#include <cuda_runtime.h>
#include <cstdint>
#include <cstddef>

#define BZ   256
#define SEQ  512
#define INS  256
#define HID  256

// ---------------------------------------------------------------------------
// helpers
// ---------------------------------------------------------------------------
__device__ __forceinline__ void ffma2(unsigned long long &acc,
                                      unsigned long long a,
                                      unsigned long long b) {
    asm volatile("fma.rn.f32x2 %0, %1, %2, %0;" : "+l"(acc) : "l"(a), "l"(b));
}
__device__ __forceinline__ unsigned long long pack2(float x, float y) {
    unsigned long long r;
    asm("mov.b64 %0, {%1, %2};" : "=l"(r) : "f"(x), "f"(y));
    return r;
}
__device__ __forceinline__ float2 unpack2(unsigned long long v) {
    float2 f;
    asm("mov.b64 {%0, %1}, %2;" : "=f"(f.x), "=f"(f.y) : "l"(v));
    return f;
}
__device__ __forceinline__ float acc_sum(unsigned long long v) {
    float2 p = unpack2(v);
    return p.x + p.y;
}
__device__ __forceinline__ unsigned smem_u32(const void* p) {
    unsigned a;
    asm("{ .reg .u64 t; cvta.to.shared.u64 t, %1; cvt.u32.u64 %0, t; }"
        : "=r"(a) : "l"(p));
    return a;
}
__device__ __forceinline__ unsigned mapa_peer(unsigned addr, unsigned peer) {
    unsigned r;
    asm("mapa.shared::cluster.u32 %0, %1, %2;" : "=r"(r) : "r"(addr), "r"(peer));
    return r;
}
__device__ __forceinline__ void st_cluster_f32(unsigned addr, float v) {
    asm volatile("st.shared::cluster.f32 [%0], %1;" :: "r"(addr), "f"(v));
}
__device__ __forceinline__ void cluster_sync_() {
    asm volatile("barrier.cluster.arrive.aligned;" ::: "memory");
    asm volatile("barrier.cluster.wait.aligned;" ::: "memory");
}
__device__ __forceinline__ void mbar_init(unsigned addr, unsigned cnt) {
    asm volatile("mbarrier.init.shared.b64 [%0], %1;" :: "r"(addr), "r"(cnt)
                 : "memory");
}
// release-arrive on a REMOTE (peer CTA) mbarrier, cluster scope
__device__ __forceinline__ void mbar_arrive_remote(unsigned remote_addr) {
    asm volatile(
        "mbarrier.arrive.release.cluster.shared::cluster.b64 _, [%0];"
        :: "r"(remote_addr) : "memory");
}
// acquire try_wait (cluster scope) on a LOCAL mbarrier, parity based
__device__ __forceinline__ void mbar_wait_acq_cluster(unsigned addr,
                                                      unsigned parity) {
    unsigned done;
    asm volatile(
        "{\n\t.reg .pred p;\n\t"
        "mbarrier.try_wait.parity.acquire.cluster.shared::cta.b64 p, [%1], %2;\n\t"
        "selp.b32 %0, 1, 0, p;\n\t}"
        : "=r"(done) : "r"(addr), "r"(parity) : "memory");
    if (!done) {
        asm volatile(
            "{\n\t.reg .pred P1;\n\t"
            "WAIT_LOOP_%=:\n\t"
            "mbarrier.try_wait.parity.acquire.cluster.shared::cta.b64 P1, [%0], %1, 0x989680;\n\t"
            "@P1 bra.uni WAIT_DONE_%=;\n\t"
            "bra.uni WAIT_LOOP_%=;\n\t"
            "WAIT_DONE_%=:\n\t}"
            :: "r"(addr), "r"(parity) : "memory");
    }
}
// fast tanh: 1 - 2/(e^{2x}+1)  via ex2.approx + rcp.approx (~1e-7 abs err)
__device__ __forceinline__ float tanh_fast(float x) {
    float e;
    asm("ex2.approx.f32 %0, %1;" : "=f"(e) : "f"(x * 2.8853900817779268f));
    float r;
    asm("rcp.approx.f32 %0, %1;" : "=f"(r) : "f"(e + 1.0f));
    return fmaf(-2.0f, r, 1.0f);
}

// ---------------------------------------------------------------------------
// Kernel 1: XU = X @ U + bias  ->  written into decoder region of d_out
// (unchanged — measured ~fp32 FMA floor)
// ---------------------------------------------------------------------------
__global__ void __launch_bounds__(256, 2) xu_kernel(
    const float* __restrict__ X, const float* __restrict__ U,
    const float* __restrict__ bias, float* __restrict__ C)
{
    __shared__ float Xs[2][16][128];
    __shared__ float Us[2][16][128];

    const int tid    = threadIdx.x;
    const int m_base = blockIdx.x * 128;
    const int n_base = blockIdx.y * 128;
    const int tx = tid & 15;
    const int ty = tid >> 4;
    const int m0 = ty * 8;
    const int n0 = tx * 8;

    const int lmx = tid >> 1;
    const int lkx = (tid & 1) * 8;
    const int lku = tid >> 4;
    const int lnu = (tid & 15) * 8;

    const float* Xg = X + (size_t)(m_base + lmx) * 256 + lkx;
    const float* Ug = U + (size_t)lku * 256 + n_base + lnu;

    float4 xa = *(const float4*)(Xg + 0);
    float4 xb = *(const float4*)(Xg + 4);
    float4 ua = *(const float4*)(Ug + 0);
    float4 ub = *(const float4*)(Ug + 4);

    int buf = 0;
    Xs[0][lkx + 0][lmx] = xa.x;  Xs[0][lkx + 1][lmx] = xa.y;
    Xs[0][lkx + 2][lmx] = xa.z;  Xs[0][lkx + 3][lmx] = xa.w;
    Xs[0][lkx + 4][lmx] = xb.x;  Xs[0][lkx + 5][lmx] = xb.y;
    Xs[0][lkx + 6][lmx] = xb.z;  Xs[0][lkx + 7][lmx] = xb.w;
    *(float4*)&Us[0][lku][lnu]     = ua;
    *(float4*)&Us[0][lku][lnu + 4] = ub;
    __syncthreads();

    unsigned long long acc[8][4];
#pragma unroll
    for (int i = 0; i < 8; i++)
#pragma unroll
        for (int j = 0; j < 4; j++) acc[i][j] = 0ULL;

    for (int kt = 0; kt < 16; kt++) {
        if (kt < 15) {
            const float* Xg2 = Xg + (kt + 1) * 16;
            const float* Ug2 = Ug + (size_t)(kt + 1) * 16 * 256;
            xa = *(const float4*)(Xg2 + 0);
            xb = *(const float4*)(Xg2 + 4);
            ua = *(const float4*)(Ug2 + 0);
            ub = *(const float4*)(Ug2 + 4);
        }
#pragma unroll
        for (int k = 0; k < 16; k++) {
            float a[8];
            *(float4*)&a[0] = *(const float4*)&Xs[buf][k][m0];
            *(float4*)&a[4] = *(const float4*)&Xs[buf][k][m0 + 4];
            ulonglong2 bq0 = *(const ulonglong2*)&Us[buf][k][n0];
            ulonglong2 bq1 = *(const ulonglong2*)&Us[buf][k][n0 + 4];
            unsigned long long bb[4] = {bq0.x, bq0.y, bq1.x, bq1.y};
#pragma unroll
            for (int i = 0; i < 8; i++) {
                unsigned long long a2 = pack2(a[i], a[i]);
                ffma2(acc[i][0], a2, bb[0]);
                ffma2(acc[i][1], a2, bb[1]);
                ffma2(acc[i][2], a2, bb[2]);
                ffma2(acc[i][3], a2, bb[3]);
            }
        }
        if (kt < 15) {
            int nb = buf ^ 1;
            Xs[nb][lkx + 0][lmx] = xa.x;  Xs[nb][lkx + 1][lmx] = xa.y;
            Xs[nb][lkx + 2][lmx] = xa.z;  Xs[nb][lkx + 3][lmx] = xa.w;
            Xs[nb][lkx + 4][lmx] = xb.x;  Xs[nb][lkx + 5][lmx] = xb.y;
            Xs[nb][lkx + 6][lmx] = xb.z;  Xs[nb][lkx + 7][lmx] = xb.w;
            *(float4*)&Us[nb][lku][lnu]     = ua;
            *(float4*)&Us[nb][lku][lnu + 4] = ub;
            __syncthreads();
            buf = nb;
        }
    }

    float b8[8];
    *(float4*)&b8[0] = *(const float4*)(bias + n_base + n0);
    *(float4*)&b8[4] = *(const float4*)(bias + n_base + n0 + 4);
#pragma unroll
    for (int i = 0; i < 8; i++) {
        float* Cr = C + (size_t)(m_base + m0 + i) * 256 + n_base + n0;
#pragma unroll
        for (int j = 0; j < 4; j++) {
            float2 p = unpack2(acc[i][j]);
            p.x += b8[2 * j];
            p.y += b8[2 * j + 1];
            *(float2*)(Cr + 2 * j) = p;
        }
    }
}

// ---------------------------------------------------------------------------
// Kernel 2: recurrence. 64 clusters x 2 CTAs x 256 thr. 4 batch rows/cluster.
// CTA rank r owns output cols [128r,128r+128) and V^T for those cols (full K).
// K split by CLUSTER HALF: group A (tid<128) uses the locally-produced k-half
// (never waits); group B (tid>=128) uses the peer half and is the only group
// that waits. Dual alternating cluster mbarriers; producer arrives on
// mbar[(t+1)&1] (single release-arrive by tid0 after __syncthreads covers all
// threads' remote stores via cumulativity); consumer waits mbar[t&1] with
// parity ((t-1)>>1)&1  [R2 bug: (t>>1)&1 deadlocked at t=2].
// ---------------------------------------------------------------------------
#define KPAD 260
#define VS_FLOATS   (128 * KPAD)                 // 33280
#define HB_FLOATS   (2 * 4 * 256)                // 2048
#define RED_FLOATS  (4 * 128)                    // 512
#define MBAR_OFF_F  (VS_FLOATS + HB_FLOATS + RED_FLOATS)   // 35840 (16B aligned)
#define RNN_SMEM_BYTES ((MBAR_OFF_F) * 4 + 32)

__global__ void __launch_bounds__(256, 1) __cluster_dims__(2, 1, 1)
rnn_kernel(const float* __restrict__ enc, const float* __restrict__ V,
           float* __restrict__ dec)
{
    extern __shared__ float smem[];
    float* Vs  = smem;                       // [128][KPAD]
    float* hb  = Vs + VS_FLOATS;             // [2][4][256]
    float* red = hb + HB_FLOATS;             // [4][128]

    const int tid = threadIdx.x;
    const int c   = tid & 127;               // column within this CTA's range
    const int g   = tid >> 7;                // 0 = local-k group, 1 = peer-k
    unsigned rk;
    asm("mov.u32 %0, %%cluster_ctarank;" : "=r"(rk));
    const unsigned peer = rk ^ 1u;
    const int cid = (int)(blockIdx.x >> 1);
    const int b0  = cid * 4;
    const int c0  = (int)rk * 128;
    const int kb  = c0 ^ (g << 7);           // k-range base for this thread

    const unsigned mbar_base = smem_u32(smem) + MBAR_OFF_F * 4u;
    if (tid == 0) {
        mbar_init(mbar_base + 0u, 1);        // arrivals at odd producer steps
        mbar_init(mbar_base + 8u, 1);        // arrivals at even producer steps
    }

    // V^T half: Vs[c][k] = V[k][c0+c], full K
    for (int i = tid; i < 128 * 256; i += 256) {
        int cl = i & 127, k = i >> 7;
        Vs[cl * KPAD + k] = V[(size_t)k * HID + c0 + cl];
    }
    // h0 = encoder rows (buffer 0) — both CTAs load full h0
    for (int i = tid; i < 4 * 256; i += 256)
        hb[i] = enc[(size_t)b0 * HID + i];
    __syncthreads();
    cluster_sync_();   // peer mbar init + both CTAs' h0 ready

    // epilogue mapping: this thread finalizes rows rr, rr+1 at column c0+c
    const int rr = g * 2;
    const size_t oA = ((size_t)(b0 + rr)     * SEQ) * HID + c0 + c;
    const size_t oB = ((size_t)(b0 + rr + 1) * SEQ) * HID + c0 + c;
    const int hiA = rr * 256 + c0 + c;       // index into one h buffer [4][256]
    const int hiB = hiA + 256;
    const int ro  = (1 - g) * 2;             // rows shipped to the other group

    const unsigned hb_a = smem_u32(hb);
    const unsigned paA[2] = { mapa_peer(hb_a + (unsigned)(hiA) * 4u, peer),
                              mapa_peer(hb_a + (unsigned)(1024 + hiA) * 4u, peer) };
    const unsigned paB[2] = { mapa_peer(hb_a + (unsigned)(hiB) * 4u, peer),
                              mapa_peer(hb_a + (unsigned)(1024 + hiB) * 4u, peer) };
    const unsigned pm[2] = { mapa_peer(mbar_base + 0u, peer),
                             mapa_peer(mbar_base + 8u, peer) };

    const float* vp = Vs + c * KPAD + kb;
    int cur = 0;

    for (int t = 0; t < SEQ; t++) {
        // prefetch xu for the 2 rows this thread finalizes (hidden by compute)
        const float xu0 = dec[oA + (size_t)t * HID];
        const float xu1 = dec[oB + (size_t)t * HID];

        // peer-k group waits for peer's h half (acquire, cluster scope)
        if (g == 1 && t > 0)
            mbar_wait_acq_cluster(mbar_base + (unsigned)((t & 1) * 8),
                                  (unsigned)(((t - 1) >> 1) & 1));

        // partials for all 4 rows over this thread's k-half (128 k)
        const float* hB = hb + cur * 1024 + kb;
        unsigned long long a0 = 0ULL, a1 = 0ULL, a2 = 0ULL, a3 = 0ULL;
#pragma unroll 8
        for (int kk = 0; kk < 128; kk += 4) {
            ulonglong2 vq = *(const ulonglong2*)(vp + kk);
            ulonglong2 h0 = *(const ulonglong2*)(hB + kk);
            ulonglong2 h1 = *(const ulonglong2*)(hB + 256 + kk);
            ulonglong2 h2 = *(const ulonglong2*)(hB + 512 + kk);
            ulonglong2 h3 = *(const ulonglong2*)(hB + 768 + kk);
            ffma2(a0, h0.x, vq.x); ffma2(a0, h0.y, vq.y);
            ffma2(a1, h1.x, vq.x); ffma2(a1, h1.y, vq.y);
            ffma2(a2, h2.x, vq.x); ffma2(a2, h2.y, vq.y);
            ffma2(a3, h3.x, vq.x); ffma2(a3, h3.y, vq.y);
        }
        float s0 = acc_sum(a0), s1 = acc_sum(a1);
        float s2 = acc_sum(a2), s3 = acc_sum(a3);

        // ship partials for the rows the OTHER group finalizes
        float shipA = (g == 0) ? s2 : s0;    // row ro
        float shipB = (g == 0) ? s3 : s1;    // row ro+1
        red[ro * 128 + c]       = shipA;
        red[(ro + 1) * 128 + c] = shipB;
        __syncthreads();                      // bar#1: partials visible

        // finalize my 2 rows
        float mineA = (g == 0) ? s0 : s2;
        float mineB = (g == 0) ? s1 : s3;
        const float v0 = tanh_fast(mineA + red[rr * 128 + c]       + xu0);
        const float v1 = tanh_fast(mineB + red[(rr + 1) * 128 + c] + xu1);

        dec[oA + (size_t)t * HID] = v0;
        dec[oB + (size_t)t * HID] = v1;

        if (t != SEQ - 1) {
            const int nxt = cur ^ 1;
            float* hn = hb + nxt * 1024;
            hn[hiA] = v0;
            hn[hiB] = v1;
            st_cluster_f32(paA[nxt], v0);
            st_cluster_f32(paB[nxt], v1);
            __syncthreads();                  // bar#2: all stores issued; red reuse safe
            if (tid == 0)
                mbar_arrive_remote(pm[(t + 1) & 1]);  // release covers whole CTA
            cur = nxt;
        }
    }
}

// ---------------------------------------------------------------------------
// launch
// ---------------------------------------------------------------------------
extern "C" void kernel_launch(void* const* d_in, const int* in_sizes, int n_in,
                              void* d_out, int out_size)
{
    const float* enc  = (const float*)d_in[0];
    const float* xdec = (const float*)d_in[1];
    const float* U    = (const float*)d_in[2];
    const float* V    = (const float*)d_in[3];
    const float* b    = (const float*)d_in[4];

    float* out = (float*)d_out;
    float* dec = out + (size_t)BZ * HID;

    cudaMemcpyAsync(out, enc, (size_t)BZ * HID * sizeof(float),
                    cudaMemcpyDeviceToDevice, 0);

    xu_kernel<<<dim3((BZ * SEQ) / 128, HID / 128), 256>>>(xdec, U, b, dec);

    cudaFuncSetAttribute(rnn_kernel,
                         cudaFuncAttributeMaxDynamicSharedMemorySize,
                         RNN_SMEM_BYTES);
    rnn_kernel<<<128, 256, RNN_SMEM_BYTES>>>(enc, V, dec);
}

// round 4
// speedup vs baseline: 1.3554x; 1.2787x over previous
#include <cuda_runtime.h>
#include <cstdint>
#include <cstddef>

#define BZ   256
#define SEQ  512
#define INS  256
#define HID  256

// ---------------------------------------------------------------------------
// helpers
// ---------------------------------------------------------------------------
__device__ __forceinline__ void ffma2(unsigned long long &acc,
                                      unsigned long long a,
                                      unsigned long long b) {
    asm volatile("fma.rn.f32x2 %0, %1, %2, %0;" : "+l"(acc) : "l"(a), "l"(b));
}
__device__ __forceinline__ unsigned long long pack2(float x, float y) {
    unsigned long long r;
    asm("mov.b64 %0, {%1, %2};" : "=l"(r) : "f"(x), "f"(y));
    return r;
}
__device__ __forceinline__ float2 unpack2(unsigned long long v) {
    float2 f;
    asm("mov.b64 {%0, %1}, %2;" : "=f"(f.x), "=f"(f.y) : "l"(v));
    return f;
}
__device__ __forceinline__ float acc_sum(unsigned long long v) {
    float2 p = unpack2(v);
    return p.x + p.y;
}
__device__ __forceinline__ unsigned smem_u32(const void* p) {
    unsigned a;
    asm("{ .reg .u64 t; cvta.to.shared.u64 t, %1; cvt.u32.u64 %0, t; }"
        : "=r"(a) : "l"(p));
    return a;
}
__device__ __forceinline__ unsigned mapa_peer(unsigned addr, unsigned peer) {
    unsigned r;
    asm("mapa.shared::cluster.u32 %0, %1, %2;" : "=r"(r) : "r"(addr), "r"(peer));
    return r;
}
__device__ __forceinline__ void st_cluster_f32(unsigned addr, float v) {
    asm volatile("st.shared::cluster.f32 [%0], %1;" :: "r"(addr), "f"(v));
}
__device__ __forceinline__ void cluster_sync_() {
    asm volatile("barrier.cluster.arrive.aligned;" ::: "memory");
    asm volatile("barrier.cluster.wait.aligned;" ::: "memory");
}
__device__ __forceinline__ void mbar_init(unsigned addr, unsigned cnt) {
    asm volatile("mbarrier.init.shared.b64 [%0], %1;" :: "r"(addr), "r"(cnt)
                 : "memory");
}
__device__ __forceinline__ void mbar_arrive_remote(unsigned remote_addr) {
    asm volatile(
        "mbarrier.arrive.release.cluster.shared::cluster.b64 _, [%0];"
        :: "r"(remote_addr) : "memory");
}
__device__ __forceinline__ void mbar_wait_acq_cluster(unsigned addr,
                                                      unsigned parity) {
    unsigned done;
    asm volatile(
        "{\n\t.reg .pred p;\n\t"
        "mbarrier.try_wait.parity.acquire.cluster.shared::cta.b64 p, [%1], %2;\n\t"
        "selp.b32 %0, 1, 0, p;\n\t}"
        : "=r"(done) : "r"(addr), "r"(parity) : "memory");
    if (!done) {
        asm volatile(
            "{\n\t.reg .pred P1;\n\t"
            "WAIT_LOOP_%=:\n\t"
            "mbarrier.try_wait.parity.acquire.cluster.shared::cta.b64 P1, [%0], %1, 0x989680;\n\t"
            "@P1 bra.uni WAIT_DONE_%=;\n\t"
            "bra.uni WAIT_LOOP_%=;\n\t"
            "WAIT_DONE_%=:\n\t}"
            :: "r"(addr), "r"(parity) : "memory");
    }
}
// fast tanh: 1 - 2/(e^{2x}+1)  via ex2.approx + rcp.approx (~1e-7 abs err)
__device__ __forceinline__ float tanh_fast(float x) {
    float e;
    asm("ex2.approx.f32 %0, %1;" : "=f"(e) : "f"(x * 2.8853900817779268f));
    float r;
    asm("rcp.approx.f32 %0, %1;" : "=f"(r) : "f"(e + 1.0f));
    return fmaf(-2.0f, r, 1.0f);
}

// ---------------------------------------------------------------------------
// Kernel 1: XU = X @ U + bias  ->  decoder region of d_out (unchanged)
// ---------------------------------------------------------------------------
__global__ void __launch_bounds__(256, 2) xu_kernel(
    const float* __restrict__ X, const float* __restrict__ U,
    const float* __restrict__ bias, float* __restrict__ C)
{
    __shared__ float Xs[2][16][128];
    __shared__ float Us[2][16][128];

    const int tid    = threadIdx.x;
    const int m_base = blockIdx.x * 128;
    const int n_base = blockIdx.y * 128;
    const int tx = tid & 15;
    const int ty = tid >> 4;
    const int m0 = ty * 8;
    const int n0 = tx * 8;

    const int lmx = tid >> 1;
    const int lkx = (tid & 1) * 8;
    const int lku = tid >> 4;
    const int lnu = (tid & 15) * 8;

    const float* Xg = X + (size_t)(m_base + lmx) * 256 + lkx;
    const float* Ug = U + (size_t)lku * 256 + n_base + lnu;

    float4 xa = *(const float4*)(Xg + 0);
    float4 xb = *(const float4*)(Xg + 4);
    float4 ua = *(const float4*)(Ug + 0);
    float4 ub = *(const float4*)(Ug + 4);

    int buf = 0;
    Xs[0][lkx + 0][lmx] = xa.x;  Xs[0][lkx + 1][lmx] = xa.y;
    Xs[0][lkx + 2][lmx] = xa.z;  Xs[0][lkx + 3][lmx] = xa.w;
    Xs[0][lkx + 4][lmx] = xb.x;  Xs[0][lkx + 5][lmx] = xb.y;
    Xs[0][lkx + 6][lmx] = xb.z;  Xs[0][lkx + 7][lmx] = xb.w;
    *(float4*)&Us[0][lku][lnu]     = ua;
    *(float4*)&Us[0][lku][lnu + 4] = ub;
    __syncthreads();

    unsigned long long acc[8][4];
#pragma unroll
    for (int i = 0; i < 8; i++)
#pragma unroll
        for (int j = 0; j < 4; j++) acc[i][j] = 0ULL;

    for (int kt = 0; kt < 16; kt++) {
        if (kt < 15) {
            const float* Xg2 = Xg + (kt + 1) * 16;
            const float* Ug2 = Ug + (size_t)(kt + 1) * 16 * 256;
            xa = *(const float4*)(Xg2 + 0);
            xb = *(const float4*)(Xg2 + 4);
            ua = *(const float4*)(Ug2 + 0);
            ub = *(const float4*)(Ug2 + 4);
        }
#pragma unroll
        for (int k = 0; k < 16; k++) {
            float a[8];
            *(float4*)&a[0] = *(const float4*)&Xs[buf][k][m0];
            *(float4*)&a[4] = *(const float4*)&Xs[buf][k][m0 + 4];
            ulonglong2 bq0 = *(const ulonglong2*)&Us[buf][k][n0];
            ulonglong2 bq1 = *(const ulonglong2*)&Us[buf][k][n0 + 4];
            unsigned long long bb[4] = {bq0.x, bq0.y, bq1.x, bq1.y};
#pragma unroll
            for (int i = 0; i < 8; i++) {
                unsigned long long a2 = pack2(a[i], a[i]);
                ffma2(acc[i][0], a2, bb[0]);
                ffma2(acc[i][1], a2, bb[1]);
                ffma2(acc[i][2], a2, bb[2]);
                ffma2(acc[i][3], a2, bb[3]);
            }
        }
        if (kt < 15) {
            int nb = buf ^ 1;
            Xs[nb][lkx + 0][lmx] = xa.x;  Xs[nb][lkx + 1][lmx] = xa.y;
            Xs[nb][lkx + 2][lmx] = xa.z;  Xs[nb][lkx + 3][lmx] = xa.w;
            Xs[nb][lkx + 4][lmx] = xb.x;  Xs[nb][lkx + 5][lmx] = xb.y;
            Xs[nb][lkx + 6][lmx] = xb.z;  Xs[nb][lkx + 7][lmx] = xb.w;
            *(float4*)&Us[nb][lku][lnu]     = ua;
            *(float4*)&Us[nb][lku][lnu + 4] = ub;
            __syncthreads();
            buf = nb;
        }
    }

    float b8[8];
    *(float4*)&b8[0] = *(const float4*)(bias + n_base + n0);
    *(float4*)&b8[4] = *(const float4*)(bias + n_base + n0 + 4);
#pragma unroll
    for (int i = 0; i < 8; i++) {
        float* Cr = C + (size_t)(m_base + m0 + i) * 256 + n_base + n0;
#pragma unroll
        for (int j = 0; j < 4; j++) {
            float2 p = unpack2(acc[i][j]);
            p.x += b8[2 * j];
            p.y += b8[2 * j + 1];
            *(float2*)(Cr + 2 * j) = p;
        }
    }
}

// ---------------------------------------------------------------------------
// Kernel 2: recurrence with REGISTER-RESIDENT V (R3 was LDS-bound: L1=66%).
// 64 clusters x 2 CTAs x 256 thr; 4 batch rows/cluster; CTA rank r owns output
// cols [128r,128r+128). V-half (128 cols x 256 k = 128KB) lives in registers:
// warp w -> k-slice of 32 (warps 0-3 local-k half: never wait; warps 4-7 peer
// half: sole waiters), lane l -> cols {l,l+32,l+64,l+96}, 128 V floats/thread.
// Per step: 8 iters x (4 broadcast h LDS.128 + 32 FFMA2), 8-way k-reduction
// through red[w][r][c] (conflict-free both directions), tanh, DSMEM exchange
// with the proven R3 dual-mbarrier protocol.
// ---------------------------------------------------------------------------
__global__ void __launch_bounds__(256, 1) __cluster_dims__(2, 1, 1)
rnn_kernel(const float* __restrict__ enc, const float* __restrict__ V,
           float* __restrict__ dec)
{
    __shared__ float hb[2 * 4 * 256];        // [2][4][256] dual h buffer
    __shared__ float red[8 * 512];           // [w][r][128]
    __shared__ __align__(16) unsigned long long mbar[2];

    const int tid = threadIdx.x;
    const int l   = tid & 31;
    const int w   = tid >> 5;                // warp 0..7
    const int g   = w >> 2;                  // 0 = local-k warps, 1 = peer-k
    unsigned rk;
    asm("mov.u32 %0, %%cluster_ctarank;" : "=r"(rk));
    const unsigned peer = rk ^ 1u;
    const int cid = (int)(blockIdx.x >> 1);
    const int b0  = cid * 4;
    const int c0  = (int)rk * 128;
    const int kb  = (c0 ^ (g << 7)) + (w & 3) * 32;   // absolute k-slice base

    const unsigned mbar_base = smem_u32(mbar);
    if (tid == 0) {
        mbar_init(mbar_base + 0u, 1);
        mbar_init(mbar_base + 8u, 1);
    }

    // ---- V into registers: Vr[cc][j] = (V[kb+2j][col], V[kb+2j+1][col]),
    //      col = c0 + l + 32*cc. 128 coalesced global loads, once.
    unsigned long long Vr[4][16];
    {
        const float* Vg = V + c0 + l;
#pragma unroll
        for (int cc = 0; cc < 4; cc++) {
            const float* Vc = Vg + 32 * cc + (size_t)kb * HID;
#pragma unroll
            for (int j = 0; j < 16; j++) {
                Vr[cc][j] = pack2(Vc[(size_t)(2 * j) * HID],
                                  Vc[(size_t)(2 * j + 1) * HID]);
            }
        }
    }

    // ---- h0 = encoder rows (buffer 0); both CTAs load full h0
    for (int i = tid; i < 4 * 256; i += 256)
        hb[i] = enc[(size_t)b0 * HID + i];
    __syncthreads();
    cluster_sync_();   // peer mbar init + h0 ready

    // finalizer mapping: thread -> col c0+c, rows rr, rr+1
    const int c  = tid & 127;
    const int rr = (tid >> 7) * 2;
    const size_t oA = ((size_t)(b0 + rr)     * SEQ) * HID + c0 + c;
    const size_t oB = ((size_t)(b0 + rr + 1) * SEQ) * HID + c0 + c;
    const int hiA = rr * 256 + c0 + c;
    const int hiB = hiA + 256;

    const unsigned hb_a = smem_u32(hb);
    const unsigned paA[2] = { mapa_peer(hb_a + (unsigned)(hiA) * 4u, peer),
                              mapa_peer(hb_a + (unsigned)(1024 + hiA) * 4u, peer) };
    const unsigned paB[2] = { mapa_peer(hb_a + (unsigned)(hiB) * 4u, peer),
                              mapa_peer(hb_a + (unsigned)(1024 + hiB) * 4u, peer) };
    const unsigned pm[2] = { mapa_peer(mbar_base + 0u, peer),
                             mapa_peer(mbar_base + 8u, peer) };

    int cur = 0;

#pragma unroll 1
    for (int t = 0; t < SEQ; t++) {
        // prefetch xu for the 2 outputs this thread finalizes
        const float xu0 = dec[oA + (size_t)t * HID];
        const float xu1 = dec[oB + (size_t)t * HID];

        // peer-k warps wait for peer's h half (acquire, cluster scope)
        if (g == 1 && t > 0)
            mbar_wait_acq_cluster(mbar_base + (unsigned)((t & 1) * 8),
                                  (unsigned)(((t - 1) >> 1) & 1));

        // ---- 4 rows x 4 cols x 32 k, V from registers, h broadcast LDS
        const float* hp = hb + cur * 1024 + kb;
        unsigned long long acc[4][4];
#pragma unroll
        for (int r = 0; r < 4; r++)
#pragma unroll
            for (int cc = 0; cc < 4; cc++) acc[r][cc] = 0ULL;

#pragma unroll
        for (int i = 0; i < 8; i++) {        // 4 k per iter
            ulonglong2 h0 = *(const ulonglong2*)(hp + 4 * i);
            ulonglong2 h1 = *(const ulonglong2*)(hp + 256 + 4 * i);
            ulonglong2 h2 = *(const ulonglong2*)(hp + 512 + 4 * i);
            ulonglong2 h3 = *(const ulonglong2*)(hp + 768 + 4 * i);
#pragma unroll
            for (int cc = 0; cc < 4; cc++) {
                ffma2(acc[0][cc], h0.x, Vr[cc][2 * i]);
                ffma2(acc[0][cc], h0.y, Vr[cc][2 * i + 1]);
                ffma2(acc[1][cc], h1.x, Vr[cc][2 * i]);
                ffma2(acc[1][cc], h1.y, Vr[cc][2 * i + 1]);
                ffma2(acc[2][cc], h2.x, Vr[cc][2 * i]);
                ffma2(acc[2][cc], h2.y, Vr[cc][2 * i + 1]);
                ffma2(acc[3][cc], h3.x, Vr[cc][2 * i]);
                ffma2(acc[3][cc], h3.y, Vr[cc][2 * i + 1]);
            }
        }

        // ---- stage partials: red[w][r][l + 32cc]  (conflict-free STS.32)
#pragma unroll
        for (int r = 0; r < 4; r++)
#pragma unroll
            for (int cc = 0; cc < 4; cc++)
                red[w * 512 + r * 128 + 32 * cc + l] = acc_sum(acc[r][cc]);
        __syncthreads();                      // bar#1

        // ---- finalize my 2 outputs: 8-way reduction over warps
        float s0 = 0.f, s1 = 0.f;
#pragma unroll
        for (int ww = 0; ww < 8; ww++) {
            s0 += red[ww * 512 + rr * 128 + c];
            s1 += red[ww * 512 + (rr + 1) * 128 + c];
        }
        const float v0 = tanh_fast(s0 + xu0);
        const float v1 = tanh_fast(s1 + xu1);

        dec[oA + (size_t)t * HID] = v0;
        dec[oB + (size_t)t * HID] = v1;

        if (t != SEQ - 1) {
            const int nxt = cur ^ 1;
            hb[nxt * 1024 + hiA] = v0;
            hb[nxt * 1024 + hiB] = v1;
            st_cluster_f32(paA[nxt], v0);
            st_cluster_f32(paB[nxt], v1);
            __syncthreads();                  // bar#2: stores issued, red reusable
            if (tid == 0)
                mbar_arrive_remote(pm[(t + 1) & 1]);
            cur = nxt;
        }
    }
}

// ---------------------------------------------------------------------------
// launch
// ---------------------------------------------------------------------------
extern "C" void kernel_launch(void* const* d_in, const int* in_sizes, int n_in,
                              void* d_out, int out_size)
{
    const float* enc  = (const float*)d_in[0];
    const float* xdec = (const float*)d_in[1];
    const float* U    = (const float*)d_in[2];
    const float* V    = (const float*)d_in[3];
    const float* b    = (const float*)d_in[4];

    float* out = (float*)d_out;
    float* dec = out + (size_t)BZ * HID;

    cudaMemcpyAsync(out, enc, (size_t)BZ * HID * sizeof(float),
                    cudaMemcpyDeviceToDevice, 0);

    xu_kernel<<<dim3((BZ * SEQ) / 128, HID / 128), 256>>>(xdec, U, b, dec);

    rnn_kernel<<<128, 256>>>(enc, V, dec);
}

// round 6
// speedup vs baseline: 1.4952x; 1.1032x over previous
#include <cuda_runtime.h>
#include <cstdint>
#include <cstddef>

#define BZ   256
#define SEQ  512
#define INS  256
#define HID  256

// ---------------------------------------------------------------------------
// helpers
// ---------------------------------------------------------------------------
__device__ __forceinline__ void ffma2(unsigned long long &acc,
                                      unsigned long long a,
                                      unsigned long long b) {
    asm volatile("fma.rn.f32x2 %0, %1, %2, %0;" : "+l"(acc) : "l"(a), "l"(b));
}
__device__ __forceinline__ unsigned long long pack2(float x, float y) {
    unsigned long long r;
    asm("mov.b64 %0, {%1, %2};" : "=l"(r) : "f"(x), "f"(y));
    return r;
}
__device__ __forceinline__ float2 unpack2(unsigned long long v) {
    float2 f;
    asm("mov.b64 {%0, %1}, %2;" : "=f"(f.x), "=f"(f.y) : "l"(v));
    return f;
}
__device__ __forceinline__ float acc_sum(unsigned long long v) {
    float2 p = unpack2(v);
    return p.x + p.y;
}
// fast tanh: 1 - 2/(e^{2x}+1)  via ex2.approx + rcp.approx (~1e-7 abs err)
__device__ __forceinline__ float tanh_fast(float x) {
    float e;
    asm("ex2.approx.f32 %0, %1;" : "=f"(e) : "f"(x * 2.8853900817779268f));
    float r;
    asm("rcp.approx.f32 %0, %1;" : "=f"(r) : "f"(e + 1.0f));
    return fmaf(-2.0f, r, 1.0f);
}

// ---------------------------------------------------------------------------
// Kernel 1: XU = X @ U + bias  ->  decoder region of d_out (unchanged)
// ---------------------------------------------------------------------------
__global__ void __launch_bounds__(256, 2) xu_kernel(
    const float* __restrict__ X, const float* __restrict__ U,
    const float* __restrict__ bias, float* __restrict__ C)
{
    __shared__ float Xs[2][16][128];
    __shared__ float Us[2][16][128];

    const int tid    = threadIdx.x;
    const int m_base = blockIdx.x * 128;
    const int n_base = blockIdx.y * 128;
    const int tx = tid & 15;
    const int ty = tid >> 4;
    const int m0 = ty * 8;
    const int n0 = tx * 8;

    const int lmx = tid >> 1;
    const int lkx = (tid & 1) * 8;
    const int lku = tid >> 4;
    const int lnu = (tid & 15) * 8;

    const float* Xg = X + (size_t)(m_base + lmx) * 256 + lkx;
    const float* Ug = U + (size_t)lku * 256 + n_base + lnu;

    float4 xa = *(const float4*)(Xg + 0);
    float4 xb = *(const float4*)(Xg + 4);
    float4 ua = *(const float4*)(Ug + 0);
    float4 ub = *(const float4*)(Ug + 4);

    int buf = 0;
    Xs[0][lkx + 0][lmx] = xa.x;  Xs[0][lkx + 1][lmx] = xa.y;
    Xs[0][lkx + 2][lmx] = xa.z;  Xs[0][lkx + 3][lmx] = xa.w;
    Xs[0][lkx + 4][lmx] = xb.x;  Xs[0][lkx + 5][lmx] = xb.y;
    Xs[0][lkx + 6][lmx] = xb.z;  Xs[0][lkx + 7][lmx] = xb.w;
    *(float4*)&Us[0][lku][lnu]     = ua;
    *(float4*)&Us[0][lku][lnu + 4] = ub;
    __syncthreads();

    unsigned long long acc[8][4];
#pragma unroll
    for (int i = 0; i < 8; i++)
#pragma unroll
        for (int j = 0; j < 4; j++) acc[i][j] = 0ULL;

    for (int kt = 0; kt < 16; kt++) {
        if (kt < 15) {
            const float* Xg2 = Xg + (kt + 1) * 16;
            const float* Ug2 = Ug + (size_t)(kt + 1) * 16 * 256;
            xa = *(const float4*)(Xg2 + 0);
            xb = *(const float4*)(Xg2 + 4);
            ua = *(const float4*)(Ug2 + 0);
            ub = *(const float4*)(Ug2 + 4);
        }
#pragma unroll
        for (int k = 0; k < 16; k++) {
            float a[8];
            *(float4*)&a[0] = *(const float4*)&Xs[buf][k][m0];
            *(float4*)&a[4] = *(const float4*)&Xs[buf][k][m0 + 4];
            ulonglong2 bq0 = *(const ulonglong2*)&Us[buf][k][n0];
            ulonglong2 bq1 = *(const ulonglong2*)&Us[buf][k][n0 + 4];
            unsigned long long bb[4] = {bq0.x, bq0.y, bq1.x, bq1.y};
#pragma unroll
            for (int i = 0; i < 8; i++) {
                unsigned long long a2 = pack2(a[i], a[i]);
                ffma2(acc[i][0], a2, bb[0]);
                ffma2(acc[i][1], a2, bb[1]);
                ffma2(acc[i][2], a2, bb[2]);
                ffma2(acc[i][3], a2, bb[3]);
            }
        }
        if (kt < 15) {
            int nb = buf ^ 1;
            Xs[nb][lkx + 0][lmx] = xa.x;  Xs[nb][lkx + 1][lmx] = xa.y;
            Xs[nb][lkx + 2][lmx] = xa.z;  Xs[nb][lkx + 3][lmx] = xa.w;
            Xs[nb][lkx + 4][lmx] = xb.x;  Xs[nb][lkx + 5][lmx] = xb.y;
            Xs[nb][lkx + 6][lmx] = xb.z;  Xs[nb][lkx + 7][lmx] = xb.w;
            *(float4*)&Us[nb][lku][lnu]     = ua;
            *(float4*)&Us[nb][lku][lnu + 4] = ub;
            __syncthreads();
            buf = nb;
        }
    }

    float b8[8];
    *(float4*)&b8[0] = *(const float4*)(bias + n_base + n0);
    *(float4*)&b8[4] = *(const float4*)(bias + n_base + n0 + 4);
#pragma unroll
    for (int i = 0; i < 8; i++) {
        float* Cr = C + (size_t)(m_base + m0 + i) * 256 + n_base + n0;
#pragma unroll
        for (int j = 0; j < 4; j++) {
            float2 p = unpack2(acc[i][j]);
            p.x += b8[2 * j];
            p.y += b8[2 * j + 1];
            *(float2*)(Cr + 2 * j) = p;
        }
    }
}

// ---------------------------------------------------------------------------
// Kernel 2 (v5): NO CLUSTER. 128 independent CTAs x 512 thr; each CTA owns 2
// batch rows and the FULL V: 20 of every warp's 32-k slice in registers
// (80 regs/thread) + 12 k in SMEM (96KB, loaded once). R4 was serialization-
// bound (2600 cyc/step vs 1024 FMA floor) on the 2-CTA DSMEM/mbarrier exchange
// with only 2 warps/SMSP; this removes all cross-CTA sync and runs 4 warps/SMSP.
// warp w: kw=w&7 -> k slice [32kw,32kw+32); cw=w>>3 -> col half; lane l ->
// cols {128cw + 32cc + l}. Per step: 128 FFMA2/thread, 8-way k-reduction in
// SMEM, tanh, h double-buffer in SMEM, 2 __syncthreads. No other sync.
// ---------------------------------------------------------------------------
#define KREG 20                      // k-rows per warp-slice held in registers
#define KSM  12                      // k-rows per warp-slice held in SMEM
#define VSM_U64S  (8 * (KSM/2) * 256)        // 12288 u64 = 96KB
#define RED_FLOATS (8 * 2 * 256)             // 4096 floats = 16KB
#define HB_FLOATS  (2 * 2 * 256)             // 1024 floats = 4KB
#define RNN_SMEM_BYTES (VSM_U64S * 8 + (RED_FLOATS + HB_FLOATS) * 4)

__global__ void __launch_bounds__(512, 1)
rnn_kernel(const float* __restrict__ enc, const float* __restrict__ V,
           float* __restrict__ dec)
{
    extern __shared__ __align__(16) unsigned long long smem_u64[];
    unsigned long long* Vsm = smem_u64;                  // [8][KSM/2][256]
    float* red = (float*)(smem_u64 + VSM_U64S);          // [8][2][256]
    float* hb  = red + RED_FLOATS;                       // [2][2][256]

    const int tid = threadIdx.x;
    const int l   = tid & 31;
    const int w   = tid >> 5;            // 0..15
    const int kw  = w & 7;               // k-slice
    const int cw  = w >> 3;              // col half
    const int b0  = blockIdx.x * 2;
    const int K   = kw * 32;             // k base of this warp's slice
    const int col = cw * 128 + l;        // base col (cc adds 32*cc)

    // ---- V regs: k in [K, K+KREG), 4 cols per thread
    unsigned long long Vr[4][KREG / 2];
    {
#pragma unroll
        for (int cc = 0; cc < 4; cc++) {
            const float* Vc = V + (size_t)K * HID + col + 32 * cc;
#pragma unroll
            for (int j = 0; j < KREG / 2; j++)
                Vr[cc][j] = pack2(Vc[(size_t)(2 * j) * HID],
                                  Vc[(size_t)(2 * j + 1) * HID]);
        }
    }
    // ---- V smem: k in [K+KREG, K+32) as k-pairs: Vsm[kw][j][c]
    for (int idx = tid; idx < VSM_U64S; idx += 512) {
        int kk = idx >> 8;                   // kw*(KSM/2) + j
        int c  = idx & 255;
        int kw2 = kk / (KSM / 2);
        int j   = kk % (KSM / 2);
        int k   = kw2 * 32 + KREG + 2 * j;
        Vsm[idx] = pack2(V[(size_t)k * HID + c], V[(size_t)(k + 1) * HID + c]);
    }
    // ---- h0 = encoder rows (buffer 0)
    if (tid < 512) {
        hb[tid] = enc[(size_t)b0 * HID + tid];
    }
    __syncthreads();

    // finalizer mapping: thread -> (row fr, col fc), one output per thread
    const int fr = tid >> 8;
    const int fc = tid & 255;
    const size_t oBase = ((size_t)(b0 + fr) * SEQ) * HID + fc;

    const int redw = kw * 512 + cw * 128 + l;   // this thread's red write base
    int cur = 0;

#pragma unroll 1
    for (int t = 0; t < SEQ; t++) {
        const float xu = dec[oBase + (size_t)t * HID];   // prefetch

        const float* h0p = hb + cur * 512 + K;           // row 0, this k slice
        const float* h1p = h0p + 256;                    // row 1

        unsigned long long acc[2][4];
#pragma unroll
        for (int r = 0; r < 2; r++)
#pragma unroll
            for (int cc = 0; cc < 4; cc++) acc[r][cc] = 0ULL;

        // ---- Part A: register V, k = K .. K+KREG
#pragma unroll
        for (int i = 0; i < KREG / 4; i++) {
            ulonglong2 h0 = *(const ulonglong2*)(h0p + 4 * i);
            ulonglong2 h1 = *(const ulonglong2*)(h1p + 4 * i);
#pragma unroll
            for (int cc = 0; cc < 4; cc++) {
                ffma2(acc[0][cc], h0.x, Vr[cc][2 * i]);
                ffma2(acc[0][cc], h0.y, Vr[cc][2 * i + 1]);
                ffma2(acc[1][cc], h1.x, Vr[cc][2 * i]);
                ffma2(acc[1][cc], h1.y, Vr[cc][2 * i + 1]);
            }
        }
        // ---- Part B: SMEM V, k = K+KREG .. K+32
        const unsigned long long* vsb = Vsm + kw * ((KSM / 2) * 256) + col;
#pragma unroll
        for (int i = 0; i < KSM / 4; i++) {
            ulonglong2 h0 = *(const ulonglong2*)(h0p + KREG + 4 * i);
            ulonglong2 h1 = *(const ulonglong2*)(h1p + KREG + 4 * i);
#pragma unroll
            for (int cc = 0; cc < 4; cc++) {
                unsigned long long v0 = vsb[(2 * i) * 256 + 32 * cc];
                unsigned long long v1 = vsb[(2 * i + 1) * 256 + 32 * cc];
                ffma2(acc[0][cc], h0.x, v0);
                ffma2(acc[0][cc], h0.y, v1);
                ffma2(acc[1][cc], h1.x, v0);
                ffma2(acc[1][cc], h1.y, v1);
            }
        }

        // ---- stage partials: red[kw][r][cw*128 + 32cc + l] (conflict-free)
#pragma unroll
        for (int r = 0; r < 2; r++)
#pragma unroll
            for (int cc = 0; cc < 4; cc++)
                red[redw + r * 256 + 32 * cc] = acc_sum(acc[r][cc]);
        __syncthreads();                      // bar#1

        // ---- finalize: 8-way reduce over kw, tanh, store
        float s = 0.f;
#pragma unroll
        for (int ww = 0; ww < 8; ww++)
            s += red[ww * 512 + fr * 256 + fc];
        const float v = tanh_fast(s + xu);

        dec[oBase + (size_t)t * HID] = v;

        const int nxt = cur ^ 1;
        hb[nxt * 512 + fr * 256 + fc] = v;
        __syncthreads();                      // bar#2: h ready, red reusable
        cur = nxt;
    }
}

// ---------------------------------------------------------------------------
// launch
// ---------------------------------------------------------------------------
extern "C" void kernel_launch(void* const* d_in, const int* in_sizes, int n_in,
                              void* d_out, int out_size)
{
    const float* enc  = (const float*)d_in[0];
    const float* xdec = (const float*)d_in[1];
    const float* U    = (const float*)d_in[2];
    const float* V    = (const float*)d_in[3];
    const float* b    = (const float*)d_in[4];

    float* out = (float*)d_out;
    float* dec = out + (size_t)BZ * HID;

    cudaMemcpyAsync(out, enc, (size_t)BZ * HID * sizeof(float),
                    cudaMemcpyDeviceToDevice, 0);

    xu_kernel<<<dim3((BZ * SEQ) / 128, HID / 128), 256>>>(xdec, U, b, dec);

    cudaFuncSetAttribute(rnn_kernel,
                         cudaFuncAttributeMaxDynamicSharedMemorySize,
                         RNN_SMEM_BYTES);
    rnn_kernel<<<128, 512, RNN_SMEM_BYTES>>>(enc, V, dec);
}